// round 4
// baseline (speedup 1.0000x reference)
#include <cuda_runtime.h>

#define BB 128
#define PP 4096
#define NN 64
#define SPLIT 4                       // P split into 4 chunks of 1024 points

// q[n](x) = K + a0*x0^2 + b0*x0 + a1*x1^2 + b1*x1,  exp(-dist) = EX2(q)
__device__ float4 g_cab[NN];          // {a0, b0, a1, b1}
__device__ float  g_k[NN];
__device__ float  g_partial[BB * SPLIT * NN];

__global__ void slayer_precompute(const float* __restrict__ centers,
                                  const float* __restrict__ sharp) {
    int n = threadIdx.x;
    if (n < NN) {
        const float L = 1.4426950408889634f;  // log2(e)
        float c0 = centers[2 * n], c1 = centers[2 * n + 1];
        float s0 = sharp[2 * n],   s1 = sharp[2 * n + 1];
        float a0 = -L * s0 * s0;
        float a1 = -L * s1 * s1;
        float b0 = -2.0f * a0 * c0;
        float b1 = -2.0f * a1 * c1;
        float K  = a0 * c0 * c0 + a1 * c1 * c1;
        g_cab[n] = make_float4(a0, b0, a1, b1);
        g_k[n]   = K;
    }
}

// grid = B*SPLIT blocks, 256 threads = 8 warps, 3 blocks/SM.
// Block (b, s) covers points [s*1024, (s+1)*1024) of batch b.
// Warp w owns centers 8w..8w+7 (coeffs in registers).
// Each lane processes 2 points per iter (float4 load) -> 16 iters,
// 16 independent EX2 chains per iteration per warp.
__global__ __launch_bounds__(256, 3) void slayer_main(
    const float4* __restrict__ batch,   // [B, P/2] of float4 (2 points)
    const float2* __restrict__ mask,    // [B, P/2] of float2
    float*        __restrict__ out_partial)
{
    const int b    = blockIdx.x >> 2;
    const int s    = blockIdx.x & 3;
    const int tid  = threadIdx.x;
    const int warp = tid >> 5;
    const int lane = tid & 31;

    float4 cab[8];
    float  kk[8];
#pragma unroll
    for (int j = 0; j < 8; j++) {
        cab[j] = g_cab[8 * warp + j];
        kk[j]  = g_k[8 * warp + j];
    }

    float acc[8];
#pragma unroll
    for (int j = 0; j < 8; j++) acc[j] = 0.0f;

    // float4 index: batch has PP/2 float4 per b; chunk s is 512 of them
    const float4* bp = batch + (size_t)b * (PP / 2) + s * (PP / 2 / SPLIT);
    const float2* mp = mask  + (size_t)b * (PP / 2) + s * (PP / 2 / SPLIT);

    constexpr int ITERS = (PP / 2 / SPLIT) / 32;   // 16

#pragma unroll 2
    for (int it = 0; it < ITERS; it++) {
        const int p = it * 32 + lane;
        const float4 x = __ldg(bp + p);   // point A = (x,y), point B = (z,w)
        const float2 m = __ldg(mp + p);

        const float xa0 = x.x * x.x, xa1 = x.y * x.y;
        const float xb0 = x.z * x.z, xb1 = x.w * x.w;

#pragma unroll
        for (int j = 0; j < 8; j++) {
            float qa = kk[j];
            qa = fmaf(cab[j].x, xa0, qa);
            qa = fmaf(cab[j].y, x.x, qa);
            qa = fmaf(cab[j].z, xa1, qa);
            qa = fmaf(cab[j].w, x.y, qa);
            float qb = kk[j];
            qb = fmaf(cab[j].x, xb0, qb);
            qb = fmaf(cab[j].y, x.z, qb);
            qb = fmaf(cab[j].z, xb1, qb);
            qb = fmaf(cab[j].w, x.w, qb);
            float ea, eb;
            asm("ex2.approx.ftz.f32 %0, %1;" : "=f"(ea) : "f"(qa));
            asm("ex2.approx.ftz.f32 %0, %1;" : "=f"(eb) : "f"(qb));
            acc[j] = fmaf(m.x, ea, acc[j]);
            acc[j] = fmaf(m.y, eb, acc[j]);
        }
    }

    // Reduce over the 32 lanes
#pragma unroll
    for (int off = 16; off > 0; off >>= 1) {
#pragma unroll
        for (int j = 0; j < 8; j++)
            acc[j] += __shfl_xor_sync(0xffffffffu, acc[j], off);
    }

    // Disjoint partial slots: no smem, no syncthreads
    if (lane == 0) {
#pragma unroll
        for (int j = 0; j < 8; j++)
            out_partial[(size_t)(b * SPLIT + s) * NN + 8 * warp + j] = acc[j];
    }
}

// out[b][n] = sum over s of partial[b][s][n]
__global__ void slayer_reduce(const float* __restrict__ partial,
                              float* __restrict__ out) {
    const int b = blockIdx.x;
    const int n = threadIdx.x;
    float v = 0.0f;
#pragma unroll
    for (int s = 0; s < SPLIT; s++)
        v += partial[(size_t)(b * SPLIT + s) * NN + n];
    out[b * NN + n] = v;
}

extern "C" void kernel_launch(void* const* d_in, const int* in_sizes, int n_in,
                              void* d_out, int out_size) {
    const float* batch   = (const float*)d_in[0];   // [B,P,D] f32
    const float* mask    = (const float*)d_in[1];   // [B,P]   f32
    const float* centers = (const float*)d_in[2];   // [N,D]   f32
    const float* sharp   = (const float*)d_in[3];   // [N,D]   f32
    float* out = (float*)d_out;                     // [B,N]   f32

    float* partial;
    cudaGetSymbolAddress((void**)&partial, g_partial);

    slayer_precompute<<<1, 64>>>(centers, sharp);
    slayer_main<<<BB * SPLIT, 256>>>((const float4*)batch,
                                     (const float2*)mask, partial);
    slayer_reduce<<<BB, NN>>>(partial, out);
}

// round 5
// speedup vs baseline: 1.2500x; 1.2500x over previous
#include <cuda_runtime.h>

#define BB 128
#define PP 4096
#define NN 64

// Single fused kernel. One block per batch b, 512 threads = 16 warps.
//   warp & 7  -> center block (8 centers, coeffs recomputed inline, kept in regs)
//   warp >> 3 -> point half (2 x 2048 points)
// Each lane handles 2 points per iteration (float4 load) -> 16 EX2 chains/warp/iter.
// q[n](x) = K + a0*x0^2 + b0*x0 + a1*x1^2 + b1*x1,  exp(-dist) = EX2(q)
__global__ __launch_bounds__(512, 1) void slayer_fused(
    const float4* __restrict__ batch,    // [B, P/2] of float4 (2 points, D=2)
    const float2* __restrict__ mask,     // [B, P/2] of float2
    const float*  __restrict__ centers,  // [N, D]
    const float*  __restrict__ sharp,    // [N, D]
    float*        __restrict__ out)      // [B, N]
{
    const int b    = blockIdx.x;
    const int tid  = threadIdx.x;
    const int warp = tid >> 5;
    const int lane = tid & 31;
    const int nb   = warp & 7;    // centers 8*nb .. 8*nb+7
    const int half = warp >> 3;

    // Inline coefficient computation for this warp's 8 centers.
    // All lanes compute identical values (broadcast loads, L1-resident).
    const float L = 1.4426950408889634f;  // log2(e)
    float A0[8], B0[8], A1[8], B1[8], KK[8], acc[8];
#pragma unroll
    for (int j = 0; j < 8; j++) {
        const int n = 8 * nb + j;
        const float c0 = __ldg(centers + 2 * n);
        const float c1 = __ldg(centers + 2 * n + 1);
        const float s0 = __ldg(sharp + 2 * n);
        const float s1 = __ldg(sharp + 2 * n + 1);
        const float a0 = -L * s0 * s0;
        const float a1 = -L * s1 * s1;
        A0[j] = a0;
        A1[j] = a1;
        B0[j] = -2.0f * a0 * c0;
        B1[j] = -2.0f * a1 * c1;
        KK[j] = a0 * c0 * c0 + a1 * c1 * c1;
        acc[j] = 0.0f;
    }

    // Point sweep: this warp's half is 2048 points = 1024 float4 entries.
    const float4* bp = batch + (size_t)b * (PP / 2) + half * (PP / 4);
    const float2* mp = mask  + (size_t)b * (PP / 2) + half * (PP / 4);

    constexpr int ITERS = (PP / 4) / 32;   // 32 iterations, 2 points each

#pragma unroll 2
    for (int it = 0; it < ITERS; it++) {
        const int p = it * 32 + lane;
        const float4 x = __ldg(bp + p);    // point A=(x,y), point B=(z,w)
        const float2 m = __ldg(mp + p);

        const float xa0 = x.x * x.x, xa1 = x.y * x.y;
        const float xb0 = x.z * x.z, xb1 = x.w * x.w;

#pragma unroll
        for (int j = 0; j < 8; j++) {
            float qa = KK[j];
            qa = fmaf(A0[j], xa0, qa);
            qa = fmaf(B0[j], x.x, qa);
            qa = fmaf(A1[j], xa1, qa);
            qa = fmaf(B1[j], x.y, qa);
            float qb = KK[j];
            qb = fmaf(A0[j], xb0, qb);
            qb = fmaf(B0[j], x.z, qb);
            qb = fmaf(A1[j], xb1, qb);
            qb = fmaf(B1[j], x.w, qb);
            float ea, eb;
            asm("ex2.approx.ftz.f32 %0, %1;" : "=f"(ea) : "f"(qa));
            asm("ex2.approx.ftz.f32 %0, %1;" : "=f"(eb) : "f"(qb));
            acc[j] = fmaf(m.x, ea, acc[j]);
            acc[j] = fmaf(m.y, eb, acc[j]);
        }
    }

    // Reduce over the 32 point-lanes
#pragma unroll
    for (int off = 16; off > 0; off >>= 1) {
#pragma unroll
        for (int j = 0; j < 8; j++)
            acc[j] += __shfl_xor_sync(0xffffffffu, acc[j], off);
    }

    // Combine the two point-halves deterministically via shared memory
    __shared__ float partial[2][NN];
    if (lane == 0) {
#pragma unroll
        for (int j = 0; j < 8; j++)
            partial[half][8 * nb + j] = acc[j];
    }
    __syncthreads();

    if (tid < NN)
        out[b * NN + tid] = partial[0][tid] + partial[1][tid];
}

extern "C" void kernel_launch(void* const* d_in, const int* in_sizes, int n_in,
                              void* d_out, int out_size) {
    const float* batch   = (const float*)d_in[0];   // [B,P,D] f32
    const float* mask    = (const float*)d_in[1];   // [B,P]   f32
    const float* centers = (const float*)d_in[2];   // [N,D]   f32
    const float* sharp   = (const float*)d_in[3];   // [N,D]   f32
    float* out = (float*)d_out;                     // [B,N]   f32

    slayer_fused<<<BB, 512>>>((const float4*)batch, (const float2*)mask,
                              centers, sharp, out);
}